// round 8
// baseline (speedup 1.0000x reference)
#include <cuda_runtime.h>
#include <cstdint>

#define LOG2E 1.4426950408889634f

// ---------------- scratch (device globals; no allocations allowed) ----------
__device__ float g_part[8 * 64];            // per (b,c) partial sums
__device__ float g_t[64];                   // relu(MLP) * log2(e)
__device__ float g_Wc[64 * 25 * 12];        // composed weights [i][tap][12]:
                                            //   slots 0..8 = k0..k8, 9 = k8 dup, 10..11 = 0
__device__ float g_bc[9 * 25];              // per-tap bias contribution [k][tap]
__device__ float g_bfield[9 * 128 * 128];   // clipped bias field [k][h][w]
__device__ float g_wtA[8 * 9 * 128 * 128];  // conv logits quarter 0 (+bfield)
__device__ float g_wtB[8 * 9 * 128 * 128];  // quarter 1
__device__ float g_wtC[8 * 9 * 128 * 128];  // quarter 2
__device__ float g_wtD[8 * 9 * 128 * 128];  // quarter 3

// ---------------- asm helpers ------------------------------------------------
__device__ __forceinline__ unsigned long long ld_s_b64(uint32_t addr) {
    unsigned long long v;
    asm volatile("ld.shared.b64 %0, [%1];" : "=l"(v) : "r"(addr));
    return v;
}
__device__ __forceinline__ void ld_s_v2u64(uint32_t addr,
                                           unsigned long long& a, unsigned long long& b) {
    asm volatile("ld.shared.v2.u64 {%0, %1}, [%2];" : "=l"(a), "=l"(b) : "r"(addr));
}
__device__ __forceinline__ void st_s_dup(uint32_t addr, float v) {
    asm volatile("st.shared.v2.f32 [%0], {%1, %2};" :: "r"(addr), "f"(v), "f"(v));
}
__device__ __forceinline__ void fma2(unsigned long long& acc,
                                     unsigned long long a, unsigned long long b) {
    asm("fma.rn.f32x2 %0, %1, %2, %0;" : "+l"(acc) : "l"(a), "l"(b));
}
__device__ __forceinline__ unsigned long long pack_ab(unsigned long long a,
                                                      unsigned long long b) {
    unsigned long long v;
    asm("mov.b64 %0, {%1, %2};" : "=l"(v) : "r"((uint32_t)a), "r"((uint32_t)b));
    return v;
}

// ---------------- P1: chansum (blocks 0..511) + compose weights (512..586) --
__global__ void k_prep1(const float* __restrict__ x, const float* __restrict__ w1,
                        const float* __restrict__ b1, const float* __restrict__ w2) {
    int blk = blockIdx.x;
    int tid = threadIdx.x;   // 256
    if (blk < 512) {
        int c = blk & 63, b = blk >> 6;
        const float4* p = (const float4*)(x + (size_t)(b * 64 + c) * 16384);
        float s0 = 0.f, s1 = 0.f, s2 = 0.f, s3 = 0.f;
        #pragma unroll
        for (int i = 0; i < 16; ++i) {
            float4 v = p[tid + i * 256];
            s0 += v.x; s1 += v.y; s2 += v.z; s3 += v.w;
        }
        float s = (s0 + s1) + (s2 + s3);
        __shared__ float sh[256];
        sh[tid] = s;
        __syncthreads();
        for (int o = 128; o > 0; o >>= 1) {
            if (tid < o) sh[tid] += sh[tid + o];
            __syncthreads();
        }
        if (tid == 0) g_part[b * 64 + c] = sh[0];
    } else {
        int idx = (blk - 512) * 256 + tid;       // 0..19199
        if (idx < 19200) {
            int i = idx / 300, rem = idx % 300;
            int tap = rem / 12, slot = rem % 12;
            float s = 0.f;
            if (slot < 10) {
                int kk = (slot >= 8) ? 8 : slot;   // slot 9 duplicates k8
                float a0 = 0.f, a1 = 0.f;
                #pragma unroll 8
                for (int o = 0; o < 64; o += 2) {
                    a0 += w2[(kk * 64 + o) * 25 + tap] * w1[o * 64 + i];
                    a1 += w2[(kk * 64 + o + 1) * 25 + tap] * w1[(o + 1) * 64 + i];
                }
                s = a0 + a1;
            }
            g_Wc[idx] = s;
        }
        if (idx < 225) {
            int k = idx / 25, tap = idx % 25;
            float s = 0.f;
            #pragma unroll 8
            for (int o = 0; o < 64; ++o)
                s += w2[(k * 64 + o) * 25 + tap] * b1[o];
            g_bc[idx] = s;
        }
    }
}

// ---------------- P2: bfield (blocks 0..63) + MLP (block 64) ----------------
__global__ void k_prep2(const float* __restrict__ tc1, const float* __restrict__ tc2) {
    int blk = blockIdx.x;
    int tid = threadIdx.x;   // 256
    if (blk == 64) {
        __shared__ float smean[64];
        __shared__ float sh1[16];
        if (tid < 64) {
            float s = 0.f;
            #pragma unroll
            for (int b = 0; b < 8; ++b) s += g_part[b * 64 + tid];
            smean[tid] = s * (1.f / 131072.f);
        }
        __syncthreads();
        if (tid < 16) {
            float a = 0.f;
            #pragma unroll
            for (int c = 0; c < 64; ++c) a += tc1[tid * 64 + c] * smean[c];
            sh1[tid] = fmaxf(a, 0.f);
        }
        __syncthreads();
        if (tid < 64) {
            float a = 0.f;
            #pragma unroll
            for (int j = 0; j < 16; ++j) a += tc2[tid * 16 + j] * sh1[j];
            g_t[tid] = fmaxf(a, 0.f) * LOG2E;
        }
        return;
    }
    __shared__ float sbc[225];
    if (tid < 225) sbc[tid] = g_bc[tid];
    __syncthreads();
    int pix = blk * 256 + tid;
    int h = pix >> 7, w = pix & 127;
    #pragma unroll
    for (int k = 0; k < 9; ++k) {
        float s = 0.f;
        #pragma unroll
        for (int dy = 0; dy < 5; ++dy) {
            int ih = h + dy - 2;
            if (ih < 0 || ih > 127) continue;
            #pragma unroll
            for (int dx = 0; dx < 5; ++dx) {
                int iw = w + dx - 2;
                if (iw < 0 || iw > 127) continue;
                s += sbc[k * 25 + dy * 5 + dx];
            }
        }
        g_bfield[k * 16384 + pix] = s;
    }
}

// ---------------- kernel D: 5x5 conv, split over cin QUARTERS ---------------
// Grid (4,8,32): 32x16 output tile; z = b*4 + quarter (16 cin each).
// Block (32,4); thread owns 4 consecutive rows, column tx.
// Dynamic smem (27840 B): [0,4800) sW (4ch x 300 fl); [4800,27840) sXp dup pairs.
// Rolling 4-row register window over dy keeps regs low for 6 CTAs/SM.
__global__ void __launch_bounds__(128, 6) k_conv(const float* __restrict__ x) {
    extern __shared__ float sdyn[];
    int tx = threadIdx.x, ty = threadIdx.y;
    int tid = ty * 32 + tx;
    int h0 = blockIdx.y * 16, w0 = blockIdx.x * 32;
    int bz = blockIdx.z >> 2;
    int q = blockIdx.z & 3;
    int cbase = q * 16;
    const float* xb = x + (size_t)bz * 64 * 16384;

    uint32_t sbase = (uint32_t)__cvta_generic_to_shared(sdyn);
    uint32_t sW = sbase;
    uint32_t sXp = sbase + 4800;

    unsigned long long acc[4][4];    // [j][pair] = k0..k7
    unsigned long long acc8[2];      // [jp] = {k8@j=2jp, k8@j=2jp+1}
    #pragma unroll
    for (int j = 0; j < 4; ++j)
        #pragma unroll
        for (int p = 0; p < 4; ++p) acc[j][p] = 0ull;
    acc8[0] = acc8[1] = 0ull;

    for (int c0 = 0; c0 < 16; c0 += 4) {
        __syncthreads();
        for (int i = tid; i < 1200; i += 128) sdyn[i] = g_Wc[(cbase + c0) * 300 + i];
        for (int i = tid; i < 2880; i += 128) {
            int c = i / 720, rem = i % 720;
            int y = rem / 36, xx = rem % 36;
            int gh = h0 + y - 2, gw = w0 + xx - 2;
            float v = 0.f;
            if (gh >= 0 && gh < 128 && gw >= 0 && gw < 128)
                v = xb[(size_t)(cbase + c0 + c) * 16384 + gh * 128 + gw];
            st_s_dup(sXp + i * 8, v);
        }
        __syncthreads();

        #pragma unroll 1
        for (int c = 0; c < 4; ++c) {
            uint32_t xbase = sXp + (c * 720 + (ty * 4) * 36 + tx) * 8;
            uint32_t wb = sW + c * 1200;

            // rolling window: xw[i] = row (dy + i), 5 dup-pair positions each
            unsigned long long xw[4][5];
            #pragma unroll
            for (int r = 0; r < 4; ++r)
                #pragma unroll
                for (int q5 = 0; q5 < 5; ++q5)
                    xw[r][q5] = ld_s_b64(xbase + r * 288 + q5 * 8);

            #pragma unroll
            for (int dy = 0; dy < 5; ++dy) {
                #pragma unroll
                for (int dx = 0; dx < 5; ++dx) {
                    uint32_t wp = wb + (dy * 5 + dx) * 48;
                    unsigned long long wv0, wv1, wv2, wv3, wv8;
                    ld_s_v2u64(wp, wv0, wv1);
                    ld_s_v2u64(wp + 16, wv2, wv3);
                    wv8 = ld_s_b64(wp + 32);
                    #pragma unroll
                    for (int jp = 0; jp < 2; ++jp) {
                        unsigned long long xa = xw[2 * jp][dx];
                        unsigned long long xc2 = xw[2 * jp + 1][dx];
                        fma2(acc[2 * jp][0], wv0, xa);
                        fma2(acc[2 * jp][1], wv1, xa);
                        fma2(acc[2 * jp][2], wv2, xa);
                        fma2(acc[2 * jp][3], wv3, xa);
                        fma2(acc[2 * jp + 1][0], wv0, xc2);
                        fma2(acc[2 * jp + 1][1], wv1, xc2);
                        fma2(acc[2 * jp + 1][2], wv2, xc2);
                        fma2(acc[2 * jp + 1][3], wv3, xc2);
                        fma2(acc8[jp], wv8, pack_ab(xa, xc2));
                    }
                }
                if (dy < 4) {
                    #pragma unroll
                    for (int r = 0; r < 3; ++r)
                        #pragma unroll
                        for (int q5 = 0; q5 < 5; ++q5)
                            xw[r][q5] = xw[r + 1][q5];
                    #pragma unroll
                    for (int q5 = 0; q5 < 5; ++q5)
                        xw[3][q5] = ld_s_b64(xbase + (dy + 4) * 288 + q5 * 8);
                }
            }
        }
    }

    float* dst = (q == 0) ? g_wtA : (q == 1) ? g_wtB : (q == 2) ? g_wtC : g_wtD;
    int w = w0 + tx;
    #pragma unroll
    for (int j = 0; j < 4; ++j) {
        int h = h0 + ty * 4 + j;
        int pix = h * 128 + w;
        float v[9];
        #pragma unroll
        for (int p = 0; p < 4; ++p) {
            v[2 * p]     = __uint_as_float((uint32_t)acc[j][p]);
            v[2 * p + 1] = __uint_as_float((uint32_t)(acc[j][p] >> 32));
        }
        unsigned long long a8 = acc8[j >> 1];
        v[8] = (j & 1) ? __uint_as_float((uint32_t)(a8 >> 32))
                       : __uint_as_float((uint32_t)a8);
        #pragma unroll
        for (int k = 0; k < 9; ++k) {
            float o = v[k];
            if (q == 0) o += g_bfield[k * 16384 + pix];   // bias only once
            dst[((size_t)bz * 9 + k) * 16384 + pix] = o;
        }
    }
}

// ---------------- kernel E: softmax(sum logits * t_c) * 3x3 reflect patches -
// Grid (64, 8, 2): block = (row pair, batch, channel half). 128 threads.
// Thread owns 2 vertically adjacent pixels -> shares 2 of 4 patch rows.
__global__ void __launch_bounds__(128) k_out(const float* __restrict__ x,
                                             float* __restrict__ out) {
    __shared__ float st[64];
    int w = threadIdx.x;       // 0..127
    int h = blockIdx.x * 2;    // rows h, h+1
    int b = blockIdx.y;
    int chalf = blockIdx.z;
    if (w < 64) st[w] = g_t[w];
    __syncthreads();

    int rm = (h == 0) ? 1 : h - 1;          // reflect
    int r1 = h, r2 = h + 1;
    int rp = (h + 1 == 127) ? 126 : h + 2;  // reflect
    int wm = (w == 0) ? 1 : w - 1;
    int wp = (w == 127) ? 126 : w + 1;

    float ak0[9], ak1[9];
    float M0 = -1e30f, M1 = -1e30f;
    #pragma unroll
    for (int k = 0; k < 9; ++k) {
        size_t i0 = ((size_t)b * 9 + k) * 16384 + r1 * 128 + w;
        float a0 = g_wtA[i0] + g_wtB[i0] + g_wtC[i0] + g_wtD[i0];
        float a1 = g_wtA[i0 + 128] + g_wtB[i0 + 128] + g_wtC[i0 + 128] + g_wtD[i0 + 128];
        ak0[k] = a0; M0 = fmaxf(M0, a0);
        ak1[k] = a1; M1 = fmaxf(M1, a1);
    }
    #pragma unroll
    for (int k = 0; k < 9; ++k) { ak0[k] -= M0; ak1[k] -= M1; }

    const float* xb = x + (size_t)b * 64 * 16384;
    int cbeg = chalf * 32;
    #pragma unroll 1
    for (int c = cbeg; c < cbeg + 32; ++c) {
        const float* xc = xb + (size_t)c * 16384;
        float t = st[c];
        // 4 rows x 3 cols shared by the two pixels
        float g[4][3];
        g[0][0] = xc[rm * 128 + wm]; g[0][1] = xc[rm * 128 + w]; g[0][2] = xc[rm * 128 + wp];
        g[1][0] = xc[r1 * 128 + wm]; g[1][1] = xc[r1 * 128 + w]; g[1][2] = xc[r1 * 128 + wp];
        g[2][0] = xc[r2 * 128 + wm]; g[2][1] = xc[r2 * 128 + w]; g[2][2] = xc[r2 * 128 + wp];
        g[3][0] = xc[rp * 128 + wm]; g[3][1] = xc[rp * 128 + w]; g[3][2] = xc[rp * 128 + wp];
        float o0, o1;
        if (t == 0.f) {
            float sA = (g[0][0] + g[0][1]) + g[0][2];
            float sB = (g[1][0] + g[1][1]) + g[1][2];
            float sC = (g[2][0] + g[2][1]) + g[2][2];
            float sD = (g[3][0] + g[3][1]) + g[3][2];
            o0 = (sA + sB + sC) * (1.f / 9.f);
            o1 = (sB + sC + sD) * (1.f / 9.f);
        } else {
            float s0 = 0.f, oo0 = 0.f, s1 = 0.f, oo1 = 0.f;
            #pragma unroll
            for (int k = 0; k < 9; ++k) {
                float e0, e1;
                asm("ex2.approx.ftz.f32 %0, %1;" : "=f"(e0) : "f"(ak0[k] * t));
                asm("ex2.approx.ftz.f32 %0, %1;" : "=f"(e1) : "f"(ak1[k] * t));
                float p0 = g[k / 3][k % 3];
                float p1 = g[k / 3 + 1][k % 3];
                s0 += e0; oo0 = fmaf(e0, p0, oo0);
                s1 += e1; oo1 = fmaf(e1, p1, oo1);
            }
            o0 = __fdividef(oo0, s0);
            o1 = __fdividef(oo1, s1);
        }
        size_t obase = (size_t)(b * 64 + c) * 16384 + r1 * 128 + w;
        out[obase] = o0;
        out[obase + 128] = o1;
    }
}

// ---------------- launch ----------------------------------------------------
extern "C" void kernel_launch(void* const* d_in, const int* in_sizes, int n_in,
                              void* d_out, int out_size) {
    const float* x   = (const float*)d_in[0];
    const float* w1  = (const float*)d_in[1];
    const float* b1  = (const float*)d_in[2];
    const float* w2  = (const float*)d_in[3];
    const float* tc1 = (const float*)d_in[4];
    const float* tc2 = (const float*)d_in[5];
    float* out = (float*)d_out;
    (void)in_sizes; (void)n_in; (void)out_size;

    k_prep1<<<587, 256>>>(x, w1, b1, w2);
    k_prep2<<<65, 256>>>(tc1, tc2);
    dim3 gc(4, 8, 32), bc(32, 4);
    k_conv<<<gc, bc, 27840>>>(x);
    dim3 ge(64, 8, 2);
    k_out<<<ge, 128>>>(x, out);
}

// round 10
// speedup vs baseline: 1.1929x; 1.1929x over previous
#include <cuda_runtime.h>
#include <cuda_fp16.h>
#include <cstdint>

#define LOG2E 1.4426950408889634f

// ---------------- scratch (device globals; no allocations allowed) ----------
__device__ float    g_part[8 * 64];           // per (b,c) partial sums
__device__ float    g_t[64];                  // relu(MLP) * log2(e)
__device__ uint32_t g_Wh[64 * 25 * 8];        // half2 weights [c][tap][8 slots]:
                                              //  s0..3={k0,k1}..{k6,k7}, s4={k8,k8}, s5..7=0
__device__ float    g_bc[9 * 25];             // per-tap bias [k][tap]
__device__ float    g_bfield[9 * 128 * 128];  // clipped bias field [k][h][w]
__device__ float    g_wt[8 * 9 * 128 * 128];  // conv logits [b][k][h][w]

__device__ __forceinline__ __half2 u2h(uint32_t u) {
    return *reinterpret_cast<__half2*>(&u);
}

// ---------------- P1: chansum (0..511) + weights (512..561) + bias (562) ----
__global__ void k_prep1(const float* __restrict__ x, const float* __restrict__ w1,
                        const float* __restrict__ b1, const float* __restrict__ w2) {
    int blk = blockIdx.x;
    int tid = threadIdx.x;   // 256
    if (blk < 512) {
        int c = blk & 63, b = blk >> 6;
        const float4* p = (const float4*)(x + (size_t)(b * 64 + c) * 16384);
        float s0 = 0.f, s1 = 0.f, s2 = 0.f, s3 = 0.f;
        #pragma unroll
        for (int i = 0; i < 16; ++i) {
            float4 v = p[tid + i * 256];
            s0 += v.x; s1 += v.y; s2 += v.z; s3 += v.w;
        }
        float s = (s0 + s1) + (s2 + s3);
        __shared__ float sh[256];
        sh[tid] = s;
        __syncthreads();
        for (int o = 128; o > 0; o >>= 1) {
            if (tid < o) sh[tid] += sh[tid + o];
            __syncthreads();
        }
        if (tid == 0) g_part[b * 64 + c] = sh[0];
    } else if (blk < 562) {
        int idx = (blk - 512) * 256 + tid;       // 0..12799
        if (idx < 12800) {
            int c = idx / 200, rem = idx % 200;
            int tap = rem / 8, slot = rem % 8;
            float f0 = 0.f, f1 = 0.f;
            if (slot < 5) {
                int k0 = (slot < 4) ? 2 * slot : 8;
                int k1 = (slot < 4) ? 2 * slot + 1 : 8;
                #pragma unroll 8
                for (int o = 0; o < 64; ++o) {
                    float wo = w1[o * 64 + c];
                    f0 += w2[(k0 * 64 + o) * 25 + tap] * wo;
                    f1 += w2[(k1 * 64 + o) * 25 + tap] * wo;
                }
            }
            __half2 h = __floats2half2_rn(f0, f1);   // low = f0 (even k)
            g_Wh[idx] = *reinterpret_cast<uint32_t*>(&h);
        }
    } else {
        if (tid < 225) {
            int k = tid / 25, tap = tid % 25;
            float s = 0.f;
            #pragma unroll 8
            for (int o = 0; o < 64; ++o)
                s += w2[(k * 64 + o) * 25 + tap] * b1[o];
            g_bc[tid] = s;
        }
    }
}

// ---------------- P2: bfield (blocks 0..63) + MLP (block 64) ----------------
__global__ void k_prep2(const float* __restrict__ tc1, const float* __restrict__ tc2) {
    int blk = blockIdx.x;
    int tid = threadIdx.x;   // 256
    if (blk == 64) {
        __shared__ float smean[64];
        __shared__ float sh1[16];
        if (tid < 64) {
            float s = 0.f;
            #pragma unroll
            for (int b = 0; b < 8; ++b) s += g_part[b * 64 + tid];
            smean[tid] = s * (1.f / 131072.f);
        }
        __syncthreads();
        if (tid < 16) {
            float a = 0.f;
            #pragma unroll
            for (int c = 0; c < 64; ++c) a += tc1[tid * 64 + c] * smean[c];
            sh1[tid] = fmaxf(a, 0.f);
        }
        __syncthreads();
        if (tid < 64) {
            float a = 0.f;
            #pragma unroll
            for (int j = 0; j < 16; ++j) a += tc2[tid * 16 + j] * sh1[j];
            g_t[tid] = fmaxf(a, 0.f) * LOG2E;
        }
        return;
    }
    __shared__ float sbc[225];
    if (tid < 225) sbc[tid] = g_bc[tid];
    __syncthreads();
    int pix = blk * 256 + tid;
    int h = pix >> 7, w = pix & 127;
    #pragma unroll
    for (int k = 0; k < 9; ++k) {
        float s = 0.f;
        #pragma unroll
        for (int dy = 0; dy < 5; ++dy) {
            int ih = h + dy - 2;
            if (ih < 0 || ih > 127) continue;
            #pragma unroll
            for (int dx = 0; dx < 5; ++dx) {
                int iw = w + dx - 2;
                if (iw < 0 || iw > 127) continue;
                s += sbc[k * 25 + dy * 5 + dx];
            }
        }
        g_bfield[k * 16384 + pix] = s;
    }
}

// ---------------- kernel D: 5x5 conv (Cin=64 -> 9), HFMA2 fp16 --------------
// Grid (4,8,8): 32x16 tile; block (32,4); thread owns 4 consecutive rows, col tx.
// x staged as duplicated half2 {v,v}; weights as half2 k-pairs.
// acc[j][p] = {k2p, k2p+1} @ px j (fp16); acc8[jp] = {k8@2jp, k8@2jp+1}.
__global__ void __launch_bounds__(128) k_conv(const float* __restrict__ x) {
    __shared__ uint32_t sW[8 * 25 * 8];    // 6400 B
    __shared__ uint32_t sX[8 * 20 * 36];   // 23040 B (dup half2 per elem)
    int tx = threadIdx.x, ty = threadIdx.y;
    int tid = ty * 32 + tx;
    int h0 = blockIdx.y * 16, w0 = blockIdx.x * 32;
    int bz = blockIdx.z;
    const float* xb = x + (size_t)bz * 64 * 16384;

    __half2 acc[4][4], acc8[2];
    #pragma unroll
    for (int j = 0; j < 4; ++j)
        #pragma unroll
        for (int p = 0; p < 4; ++p) acc[j][p] = __floats2half2_rn(0.f, 0.f);
    acc8[0] = acc8[1] = __floats2half2_rn(0.f, 0.f);

    for (int c0 = 0; c0 < 64; c0 += 8) {
        __syncthreads();
        // stage weights: 8ch x 25 taps x 8 slots
        #pragma unroll
        for (int it = 0; it < 13; ++it) {
            int i = tid + it * 128;
            if (i < 1600) sW[i] = g_Wh[c0 * 200 + i];
        }
        // stage x tile: 8ch x 20 x 36 dup half2, zero pad
        #pragma unroll 5
        for (int i = tid; i < 5760; i += 128) {
            int c = i / 720, rem = i % 720;
            int y = rem / 36, xx = rem % 36;
            int gh = h0 + y - 2, gw = w0 + xx - 2;
            float v = 0.f;
            if (gh >= 0 && gh < 128 && gw >= 0 && gw < 128)
                v = xb[(size_t)(c0 + c) * 16384 + gh * 128 + gw];
            __half2 hv = __float2half2_rn(v);
            sX[i] = *reinterpret_cast<uint32_t*>(&hv);
        }
        __syncthreads();

        #pragma unroll 1
        for (int c = 0; c < 8; ++c) {
            // x register window: 8 rows x 5 cols (dup half2)
            const uint32_t* xbase = sX + c * 720 + (ty * 4) * 36 + tx;
            uint32_t xw[8][5];
            #pragma unroll
            for (int r = 0; r < 8; ++r)
                #pragma unroll
                for (int q = 0; q < 5; ++q)
                    xw[r][q] = xbase[r * 36 + q];

            const uint32_t* wc = sW + c * 200;
            #pragma unroll
            for (int dy = 0; dy < 5; ++dy) {
                #pragma unroll
                for (int dx = 0; dx < 5; ++dx) {
                    int tap = dy * 5 + dx;
                    uint4 wv = *reinterpret_cast<const uint4*>(wc + tap * 8);
                    uint32_t p4 = wc[tap * 8 + 4];
                    __half2 w0h = u2h(wv.x), w1h = u2h(wv.y),
                            w2h = u2h(wv.z), w3h = u2h(wv.w);
                    #pragma unroll
                    for (int jp = 0; jp < 2; ++jp) {
                        uint32_t xa = xw[2 * jp + dy][dx];
                        uint32_t xb2 = xw[2 * jp + 1 + dy][dx];
                        __half2 ha = u2h(xa), hb = u2h(xb2);
                        acc[2 * jp][0] = __hfma2(w0h, ha, acc[2 * jp][0]);
                        acc[2 * jp][1] = __hfma2(w1h, ha, acc[2 * jp][1]);
                        acc[2 * jp][2] = __hfma2(w2h, ha, acc[2 * jp][2]);
                        acc[2 * jp][3] = __hfma2(w3h, ha, acc[2 * jp][3]);
                        acc[2 * jp + 1][0] = __hfma2(w0h, hb, acc[2 * jp + 1][0]);
                        acc[2 * jp + 1][1] = __hfma2(w1h, hb, acc[2 * jp + 1][1]);
                        acc[2 * jp + 1][2] = __hfma2(w2h, hb, acc[2 * jp + 1][2]);
                        acc[2 * jp + 1][3] = __hfma2(w3h, hb, acc[2 * jp + 1][3]);
                        uint32_t xab = __byte_perm(xa, xb2, 0x5410); // {a.lo, b.lo}
                        acc8[jp] = __hfma2(u2h(p4), u2h(xab), acc8[jp]);
                    }
                }
            }
        }
    }

    int w = w0 + tx;
    #pragma unroll
    for (int j = 0; j < 4; ++j) {
        int h = h0 + ty * 4 + j;
        int pix = h * 128 + w;
        float v[9];
        #pragma unroll
        for (int p = 0; p < 4; ++p) {
            v[2 * p]     = __low2float(acc[j][p]);
            v[2 * p + 1] = __high2float(acc[j][p]);
        }
        v[8] = (j & 1) ? __high2float(acc8[j >> 1]) : __low2float(acc8[j >> 1]);
        #pragma unroll
        for (int k = 0; k < 9; ++k)
            g_wt[((size_t)bz * 9 + k) * 16384 + pix] = v[k] + g_bfield[k * 16384 + pix];
    }
}

// ---------------- kernel E: softmax(wt_k * t_c) * 3x3 reflect patches -------
// Grid (64, 8, 4): (row pair, batch, channel quarter). 128 threads, 2 px each.
__global__ void __launch_bounds__(128) k_out(const float* __restrict__ x,
                                             float* __restrict__ out) {
    __shared__ float st[64];
    int w = threadIdx.x;
    int h = blockIdx.x * 2;
    int b = blockIdx.y;
    int cq = blockIdx.z;
    if (w < 64) st[w] = g_t[w];
    __syncthreads();

    int rm = (h == 0) ? 1 : h - 1;
    int r1 = h, r2 = h + 1;
    int rp = (h + 1 == 127) ? 126 : h + 2;
    int wm = (w == 0) ? 1 : w - 1;
    int wp = (w == 127) ? 126 : w + 1;

    float ak0[9], ak1[9];
    float M0 = -1e30f, M1 = -1e30f;
    #pragma unroll
    for (int k = 0; k < 9; ++k) {
        size_t i0 = ((size_t)b * 9 + k) * 16384 + r1 * 128 + w;
        float a0 = g_wt[i0], a1 = g_wt[i0 + 128];
        ak0[k] = a0; M0 = fmaxf(M0, a0);
        ak1[k] = a1; M1 = fmaxf(M1, a1);
    }
    #pragma unroll
    for (int k = 0; k < 9; ++k) { ak0[k] -= M0; ak1[k] -= M1; }

    const float* xb = x + (size_t)b * 64 * 16384;
    int cbeg = cq * 16;
    #pragma unroll 1
    for (int c = cbeg; c < cbeg + 16; ++c) {
        const float* xc = xb + (size_t)c * 16384;
        float t = st[c];
        float g[4][3];
        g[0][0] = xc[rm * 128 + wm]; g[0][1] = xc[rm * 128 + w]; g[0][2] = xc[rm * 128 + wp];
        g[1][0] = xc[r1 * 128 + wm]; g[1][1] = xc[r1 * 128 + w]; g[1][2] = xc[r1 * 128 + wp];
        g[2][0] = xc[r2 * 128 + wm]; g[2][1] = xc[r2 * 128 + w]; g[2][2] = xc[r2 * 128 + wp];
        g[3][0] = xc[rp * 128 + wm]; g[3][1] = xc[rp * 128 + w]; g[3][2] = xc[rp * 128 + wp];
        float o0, o1;
        if (t == 0.f) {
            float sA = (g[0][0] + g[0][1]) + g[0][2];
            float sB = (g[1][0] + g[1][1]) + g[1][2];
            float sC = (g[2][0] + g[2][1]) + g[2][2];
            float sD = (g[3][0] + g[3][1]) + g[3][2];
            o0 = (sA + sB + sC) * (1.f / 9.f);
            o1 = (sB + sC + sD) * (1.f / 9.f);
        } else {
            float s0 = 0.f, oo0 = 0.f, s1 = 0.f, oo1 = 0.f;
            #pragma unroll
            for (int k = 0; k < 9; ++k) {
                float e0, e1;
                asm("ex2.approx.ftz.f32 %0, %1;" : "=f"(e0) : "f"(ak0[k] * t));
                asm("ex2.approx.ftz.f32 %0, %1;" : "=f"(e1) : "f"(ak1[k] * t));
                float p0 = g[k / 3][k % 3];
                float p1 = g[k / 3 + 1][k % 3];
                s0 += e0; oo0 = fmaf(e0, p0, oo0);
                s1 += e1; oo1 = fmaf(e1, p1, oo1);
            }
            o0 = __fdividef(oo0, s0);
            o1 = __fdividef(oo1, s1);
        }
        size_t obase = (size_t)(b * 64 + c) * 16384 + r1 * 128 + w;
        out[obase] = o0;
        out[obase + 128] = o1;
    }
}

// ---------------- launch ----------------------------------------------------
extern "C" void kernel_launch(void* const* d_in, const int* in_sizes, int n_in,
                              void* d_out, int out_size) {
    const float* x   = (const float*)d_in[0];
    const float* w1  = (const float*)d_in[1];
    const float* b1  = (const float*)d_in[2];
    const float* w2  = (const float*)d_in[3];
    const float* tc1 = (const float*)d_in[4];
    const float* tc2 = (const float*)d_in[5];
    float* out = (float*)d_out;
    (void)in_sizes; (void)n_in; (void)out_size;

    k_prep1<<<563, 256>>>(x, w1, b1, w2);
    k_prep2<<<65, 256>>>(tc1, tc2);
    dim3 gc(4, 8, 8), bc(32, 4);
    k_conv<<<gc, bc>>>(x);
    dim3 ge(64, 8, 4);
    k_out<<<ge, 128>>>(x, out);
}

// round 11
// speedup vs baseline: 1.2401x; 1.0395x over previous
#include <cuda_runtime.h>
#include <cuda_fp16.h>
#include <cstdint>

#define LOG2E 1.4426950408889634f

// ---------------- scratch (device globals; no allocations allowed) ----------
__device__ float    g_part[8 * 64];           // per (b,c) partial sums
__device__ float    g_t[64];                  // relu(MLP) * log2(e)
__device__ uint32_t g_Wh[64 * 25 * 8];        // half2 weights [c][tap][8 slots]:
                                              //  s0..3={k0,k1}..{k6,k7}, s4={k8,k8}, s5..7=0
__device__ float    g_bc[9 * 25];             // per-tap bias [k][tap]
__device__ float    g_bfield[9 * 128 * 128];  // clipped bias field [k][h][w]
__device__ float    g_wt[8 * 9 * 128 * 128];  // conv logits [b][k][h][w]

__device__ __forceinline__ __half2 u2h(uint32_t u) {
    return *reinterpret_cast<__half2*>(&u);
}

// ---------------- P1: chansum (0..511) + weights (512..561) + bias (562) ----
__global__ void k_prep1(const float* __restrict__ x, const float* __restrict__ w1,
                        const float* __restrict__ b1, const float* __restrict__ w2) {
    int blk = blockIdx.x;
    int tid = threadIdx.x;   // 256
    if (blk < 512) {
        int c = blk & 63, b = blk >> 6;
        const float4* p = (const float4*)(x + (size_t)(b * 64 + c) * 16384);
        float s0 = 0.f, s1 = 0.f, s2 = 0.f, s3 = 0.f;
        #pragma unroll
        for (int i = 0; i < 16; ++i) {
            float4 v = p[tid + i * 256];
            s0 += v.x; s1 += v.y; s2 += v.z; s3 += v.w;
        }
        float s = (s0 + s1) + (s2 + s3);
        __shared__ float sh[256];
        sh[tid] = s;
        __syncthreads();
        for (int o = 128; o > 0; o >>= 1) {
            if (tid < o) sh[tid] += sh[tid + o];
            __syncthreads();
        }
        if (tid == 0) g_part[b * 64 + c] = sh[0];
    } else if (blk < 562) {
        int idx = (blk - 512) * 256 + tid;       // 0..12799
        if (idx < 12800) {
            int c = idx / 200, rem = idx % 200;
            int tap = rem / 8, slot = rem % 8;
            float f0 = 0.f, f1 = 0.f;
            if (slot < 5) {
                int k0 = (slot < 4) ? 2 * slot : 8;
                int k1 = (slot < 4) ? 2 * slot + 1 : 8;
                #pragma unroll 8
                for (int o = 0; o < 64; ++o) {
                    float wo = w1[o * 64 + c];
                    f0 += w2[(k0 * 64 + o) * 25 + tap] * wo;
                    f1 += w2[(k1 * 64 + o) * 25 + tap] * wo;
                }
            }
            __half2 h = __floats2half2_rn(f0, f1);   // low = f0 (even k)
            g_Wh[idx] = *reinterpret_cast<uint32_t*>(&h);
        }
    } else {
        if (tid < 225) {
            int k = tid / 25, tap = tid % 25;
            float s = 0.f;
            #pragma unroll 8
            for (int o = 0; o < 64; ++o)
                s += w2[(k * 64 + o) * 25 + tap] * b1[o];
            g_bc[tid] = s;
        }
    }
}

// ---------------- P2: bfield (blocks 0..63) + MLP (block 64) ----------------
__global__ void k_prep2(const float* __restrict__ tc1, const float* __restrict__ tc2) {
    int blk = blockIdx.x;
    int tid = threadIdx.x;   // 256
    if (blk == 64) {
        __shared__ float smean[64];
        __shared__ float sh1[16];
        if (tid < 64) {
            float s = 0.f;
            #pragma unroll
            for (int b = 0; b < 8; ++b) s += g_part[b * 64 + tid];
            smean[tid] = s * (1.f / 131072.f);
        }
        __syncthreads();
        if (tid < 16) {
            float a = 0.f;
            #pragma unroll
            for (int c = 0; c < 64; ++c) a += tc1[tid * 64 + c] * smean[c];
            sh1[tid] = fmaxf(a, 0.f);
        }
        __syncthreads();
        if (tid < 64) {
            float a = 0.f;
            #pragma unroll
            for (int j = 0; j < 16; ++j) a += tc2[tid * 16 + j] * sh1[j];
            g_t[tid] = fmaxf(a, 0.f) * LOG2E;
        }
        return;
    }
    __shared__ float sbc[225];
    if (tid < 225) sbc[tid] = g_bc[tid];
    __syncthreads();
    int pix = blk * 256 + tid;
    int h = pix >> 7, w = pix & 127;
    #pragma unroll
    for (int k = 0; k < 9; ++k) {
        float s = 0.f;
        #pragma unroll
        for (int dy = 0; dy < 5; ++dy) {
            int ih = h + dy - 2;
            if (ih < 0 || ih > 127) continue;
            #pragma unroll
            for (int dx = 0; dx < 5; ++dx) {
                int iw = w + dx - 2;
                if (iw < 0 || iw > 127) continue;
                s += sbc[k * 25 + dy * 5 + dx];
            }
        }
        g_bfield[k * 16384 + pix] = s;
    }
}

// ---------------- kernel D: 5x5 conv, HFMA2, double-buffered staging --------
// Grid (4,8,8): 32x16 tile; block (32,4); thread owns 4 consecutive rows, col tx.
// Dynamic smem (58880 B): sW[2][1600] u32 at 0; sX[2][5760] u32 at 12800 B.
// While computing chunk i from buf, stage chunk i+1 into buf^1 (LDG latency
// hides under ~3600 cycles of HFMA2); barrier drains STS at iteration end.
__global__ void __launch_bounds__(128) k_conv(const float* __restrict__ x) {
    extern __shared__ uint32_t sdyn[];
    uint32_t* sWs = sdyn;            // 2 x 1600
    uint32_t* sXs = sdyn + 3200;     // 2 x 5760
    int tx = threadIdx.x, ty = threadIdx.y;
    int tid = ty * 32 + tx;
    int h0 = blockIdx.y * 16, w0 = blockIdx.x * 32;
    int bz = blockIdx.z;
    const float* xb = x + (size_t)bz * 64 * 16384;

    __half2 acc[4][4], acc8[2];
    #pragma unroll
    for (int j = 0; j < 4; ++j)
        #pragma unroll
        for (int p = 0; p < 4; ++p) acc[j][p] = __floats2half2_rn(0.f, 0.f);
    acc8[0] = acc8[1] = __floats2half2_rn(0.f, 0.f);

    // --- stage chunk 0 into buffer 0 ---
    #pragma unroll
    for (int it = 0; it < 13; ++it) {
        int i = tid + it * 128;
        if (i < 1600) sWs[i] = g_Wh[i];
    }
    #pragma unroll
    for (int it = 0; it < 45; ++it) {
        int i = tid + it * 128;
        int c = i / 720, rem = i % 720;
        int y = rem / 36, xx = rem % 36;
        int gh = h0 + y - 2, gw = w0 + xx - 2;
        float v = 0.f;
        if (gh >= 0 && gh < 128 && gw >= 0 && gw < 128)
            v = xb[(size_t)c * 16384 + gh * 128 + gw];
        __half2 hv = __float2half2_rn(v);
        sXs[i] = *reinterpret_cast<uint32_t*>(&hv);
    }
    __syncthreads();

    #pragma unroll 1
    for (int ch = 0; ch < 8; ++ch) {
        int cur = ch & 1;
        // --- prefetch next chunk into other buffer (overlaps compute) ---
        if (ch < 7) {
            int nb = cur ^ 1;
            int cb = (ch + 1) * 8;
            #pragma unroll
            for (int it = 0; it < 13; ++it) {
                int i = tid + it * 128;
                if (i < 1600) sWs[nb * 1600 + i] = g_Wh[cb * 200 + i];
            }
            #pragma unroll
            for (int it = 0; it < 45; ++it) {
                int i = tid + it * 128;
                int c = i / 720, rem = i % 720;
                int y = rem / 36, xx = rem % 36;
                int gh = h0 + y - 2, gw = w0 + xx - 2;
                float v = 0.f;
                if (gh >= 0 && gh < 128 && gw >= 0 && gw < 128)
                    v = xb[(size_t)(cb + c) * 16384 + gh * 128 + gw];
                __half2 hv = __float2half2_rn(v);
                sXs[nb * 5760 + i] = *reinterpret_cast<uint32_t*>(&hv);
            }
        }
        // --- compute from current buffer ---
        #pragma unroll 1
        for (int c = 0; c < 8; ++c) {
            const uint32_t* xbase = sXs + cur * 5760 + c * 720 + (ty * 4) * 36 + tx;
            uint32_t xw[8][5];
            #pragma unroll
            for (int r = 0; r < 8; ++r)
                #pragma unroll
                for (int q = 0; q < 5; ++q)
                    xw[r][q] = xbase[r * 36 + q];

            const uint32_t* wc = sWs + cur * 1600 + c * 200;
            #pragma unroll
            for (int dy = 0; dy < 5; ++dy) {
                #pragma unroll
                for (int dx = 0; dx < 5; ++dx) {
                    int tap = dy * 5 + dx;
                    uint4 wv = *reinterpret_cast<const uint4*>(wc + tap * 8);
                    uint32_t p4 = wc[tap * 8 + 4];
                    __half2 w0h = u2h(wv.x), w1h = u2h(wv.y),
                            w2h = u2h(wv.z), w3h = u2h(wv.w);
                    #pragma unroll
                    for (int jp = 0; jp < 2; ++jp) {
                        uint32_t xa = xw[2 * jp + dy][dx];
                        uint32_t xb2 = xw[2 * jp + 1 + dy][dx];
                        __half2 ha = u2h(xa), hb = u2h(xb2);
                        acc[2 * jp][0] = __hfma2(w0h, ha, acc[2 * jp][0]);
                        acc[2 * jp][1] = __hfma2(w1h, ha, acc[2 * jp][1]);
                        acc[2 * jp][2] = __hfma2(w2h, ha, acc[2 * jp][2]);
                        acc[2 * jp][3] = __hfma2(w3h, ha, acc[2 * jp][3]);
                        acc[2 * jp + 1][0] = __hfma2(w0h, hb, acc[2 * jp + 1][0]);
                        acc[2 * jp + 1][1] = __hfma2(w1h, hb, acc[2 * jp + 1][1]);
                        acc[2 * jp + 1][2] = __hfma2(w2h, hb, acc[2 * jp + 1][2]);
                        acc[2 * jp + 1][3] = __hfma2(w3h, hb, acc[2 * jp + 1][3]);
                        uint32_t xab = __byte_perm(xa, xb2, 0x5410); // {a.lo, b.lo}
                        acc8[jp] = __hfma2(u2h(p4), u2h(xab), acc8[jp]);
                    }
                }
            }
        }
        __syncthreads();
    }

    int w = w0 + tx;
    #pragma unroll
    for (int j = 0; j < 4; ++j) {
        int h = h0 + ty * 4 + j;
        int pix = h * 128 + w;
        float v[9];
        #pragma unroll
        for (int p = 0; p < 4; ++p) {
            v[2 * p]     = __low2float(acc[j][p]);
            v[2 * p + 1] = __high2float(acc[j][p]);
        }
        v[8] = (j & 1) ? __high2float(acc8[j >> 1]) : __low2float(acc8[j >> 1]);
        #pragma unroll
        for (int k = 0; k < 9; ++k)
            g_wt[((size_t)bz * 9 + k) * 16384 + pix] = v[k] + g_bfield[k * 16384 + pix];
    }
}

// ---------------- kernel E: softmax(wt_k * t_c) * 3x3 reflect patches -------
// Grid (64, 8, 8): (row pair, batch, channel eighth). 128 threads, 2 px each.
__global__ void __launch_bounds__(128) k_out(const float* __restrict__ x,
                                             float* __restrict__ out) {
    __shared__ float st[64];
    int w = threadIdx.x;
    int h = blockIdx.x * 2;
    int b = blockIdx.y;
    int ce = blockIdx.z;
    if (w < 64) st[w] = g_t[w];
    __syncthreads();

    int rm = (h == 0) ? 1 : h - 1;
    int r1 = h, r2 = h + 1;
    int rp = (h + 1 == 127) ? 126 : h + 2;
    int wm = (w == 0) ? 1 : w - 1;
    int wp = (w == 127) ? 126 : w + 1;

    float ak0[9], ak1[9];
    float M0 = -1e30f, M1 = -1e30f;
    #pragma unroll
    for (int k = 0; k < 9; ++k) {
        size_t i0 = ((size_t)b * 9 + k) * 16384 + r1 * 128 + w;
        float a0 = g_wt[i0], a1 = g_wt[i0 + 128];
        ak0[k] = a0; M0 = fmaxf(M0, a0);
        ak1[k] = a1; M1 = fmaxf(M1, a1);
    }
    #pragma unroll
    for (int k = 0; k < 9; ++k) { ak0[k] -= M0; ak1[k] -= M1; }

    const float* xb = x + (size_t)b * 64 * 16384;
    int cbeg = ce * 8;
    #pragma unroll 2
    for (int c = cbeg; c < cbeg + 8; ++c) {
        const float* xc = xb + (size_t)c * 16384;
        float t = st[c];
        float g[4][3];
        g[0][0] = xc[rm * 128 + wm]; g[0][1] = xc[rm * 128 + w]; g[0][2] = xc[rm * 128 + wp];
        g[1][0] = xc[r1 * 128 + wm]; g[1][1] = xc[r1 * 128 + w]; g[1][2] = xc[r1 * 128 + wp];
        g[2][0] = xc[r2 * 128 + wm]; g[2][1] = xc[r2 * 128 + w]; g[2][2] = xc[r2 * 128 + wp];
        g[3][0] = xc[rp * 128 + wm]; g[3][1] = xc[rp * 128 + w]; g[3][2] = xc[rp * 128 + wp];
        float o0, o1;
        if (t == 0.f) {
            float sA = (g[0][0] + g[0][1]) + g[0][2];
            float sB = (g[1][0] + g[1][1]) + g[1][2];
            float sC = (g[2][0] + g[2][1]) + g[2][2];
            float sD = (g[3][0] + g[3][1]) + g[3][2];
            o0 = (sA + sB + sC) * (1.f / 9.f);
            o1 = (sB + sC + sD) * (1.f / 9.f);
        } else {
            float s0 = 0.f, oo0 = 0.f, s1 = 0.f, oo1 = 0.f;
            #pragma unroll
            for (int k = 0; k < 9; ++k) {
                float e0, e1;
                asm("ex2.approx.ftz.f32 %0, %1;" : "=f"(e0) : "f"(ak0[k] * t));
                asm("ex2.approx.ftz.f32 %0, %1;" : "=f"(e1) : "f"(ak1[k] * t));
                float p0 = g[k / 3][k % 3];
                float p1 = g[k / 3 + 1][k % 3];
                s0 += e0; oo0 = fmaf(e0, p0, oo0);
                s1 += e1; oo1 = fmaf(e1, p1, oo1);
            }
            o0 = __fdividef(oo0, s0);
            o1 = __fdividef(oo1, s1);
        }
        size_t obase = (size_t)(b * 64 + c) * 16384 + r1 * 128 + w;
        out[obase] = o0;
        out[obase + 128] = o1;
    }
}

// ---------------- launch ----------------------------------------------------
extern "C" void kernel_launch(void* const* d_in, const int* in_sizes, int n_in,
                              void* d_out, int out_size) {
    const float* x   = (const float*)d_in[0];
    const float* w1  = (const float*)d_in[1];
    const float* b1  = (const float*)d_in[2];
    const float* w2  = (const float*)d_in[3];
    const float* tc1 = (const float*)d_in[4];
    const float* tc2 = (const float*)d_in[5];
    float* out = (float*)d_out;
    (void)in_sizes; (void)n_in; (void)out_size;

    static bool attr_set = false;
    if (!attr_set) {
        cudaFuncSetAttribute(k_conv, cudaFuncAttributeMaxDynamicSharedMemorySize, 58880);
        attr_set = true;
    }

    k_prep1<<<563, 256>>>(x, w1, b1, w2);
    k_prep2<<<65, 256>>>(tc1, tc2);
    dim3 gc(4, 8, 8), bc(32, 4);
    k_conv<<<gc, bc, 58880>>>(x);
    dim3 ge(64, 8, 8);
    k_out<<<ge, 128>>>(x, out);
}